// round 9
// baseline (speedup 1.0000x reference)
#include <cuda_runtime.h>

#define HW      (128 * 128)     // rays
#define KPRIM   32
#define MM      16
#define NSTEPS  64
#define DTSTEP  (1.0f / 64.0f)

// Repacked template: [k][z][y][x][c], c fastest (float4 per voxel). 2 MB.
__device__ float g_tpl[KPRIM * MM * MM * MM * 4];

// ---------------------------------------------------------------------------
// Repack kernel: template[b=0][k][c][z][y][x]  ->  g_tpl[k][z][y][x][c]
// ---------------------------------------------------------------------------
__global__ void repack_kernel(const float* __restrict__ tpl) {
    int i = blockIdx.x * blockDim.x + threadIdx.x;
    const int N = KPRIM * 4 * MM * MM * MM;  // 524288
    if (i >= N) return;
    int x = i & 15;  int t = i >> 4;
    int y = t & 15;  t >>= 4;
    int z = t & 15;  t >>= 4;
    int c = t & 3;   int k = t >> 2;
    g_tpl[((((k * 16 + z) * 16 + y) * 16 + x) << 2) + c] = tpl[i];
}

// Channel-split warp reduction of sp (float4) over 32 lanes:
//   lanes 0-7 end with sum(x), 8-15 sum(y), 16-23 sum(z), 24-31 sum(w).
//   7 shuffles total; then composite into (chacc, alpha).
#define REDUCE_COMPOSITE()                                                    \
    do {                                                                      \
        float p0 = __shfl_xor_sync(FULL, hi16 ? sp.x : sp.z, 16);             \
        float p1 = __shfl_xor_sync(FULL, hi16 ? sp.y : sp.w, 16);             \
        float a0 = (hi16 ? sp.z : sp.x) + p0;                                 \
        float a1 = (hi16 ? sp.w : sp.y) + p1;                                 \
        float q  = __shfl_xor_sync(FULL, hi8 ? a0 : a1, 8);                   \
        float acc = (hi8 ? a1 : a0) + q;                                      \
        acc += __shfl_xor_sync(FULL, acc, 4);                                 \
        acc += __shfl_xor_sync(FULL, acc, 2);                                 \
        acc += __shfl_xor_sync(FULL, acc, 1);                                 \
        float aw = __shfl_sync(FULL, acc, 24);                                \
        float na = fminf(fmaf(aw, DTSTEP, alpha), 1.0f);                      \
        float contrib = na - alpha;                                           \
        chacc = fmaf(acc, contrib, chacc);                                    \
        alpha = na;                                                           \
    } while (0)

// ---------------------------------------------------------------------------
// March kernel: one warp per ray, one lane per primitive (K == 32).
// inside(t) is an exact interval [lt0, lt1] per lane (box is convex), so the
// per-step test is 2 compares; warp loop bounds are the union of intervals.
// Reduction of step i-1 is pipelined under the gather of step i.
// ---------------------------------------------------------------------------
__global__ void __launch_bounds__(256, 3) march_kernel(
    const float* __restrict__ raypos,
    const float* __restrict__ raydir,
    const float* __restrict__ tminmax,
    const float* __restrict__ primpos,
    const float* __restrict__ primrot,
    const float* __restrict__ primscale,
    float* __restrict__ out)
{
    const unsigned FULL = 0xffffffffu;
    int gwarp = (blockIdx.x * blockDim.x + threadIdx.x) >> 5;
    int lane  = threadIdx.x & 31;
    if (gwarp >= HW) return;
    const int r = gwarp;   // ray index

    // ---- per-lane primitive constants (lane == prim index) ----
    float px = primpos[lane * 3 + 0];
    float py = primpos[lane * 3 + 1];
    float pz = primpos[lane * 3 + 2];
    float s0 = primscale[lane * 3 + 0];
    float s1 = primscale[lane * 3 + 1];
    float s2 = primscale[lane * 3 + 2];
    const float* Rm = primrot + lane * 9;
    float r00 = Rm[0] * s0, r01 = Rm[1] * s0, r02 = Rm[2] * s0;
    float r10 = Rm[3] * s1, r11 = Rm[4] * s1, r12 = Rm[5] * s1;
    float r20 = Rm[6] * s2, r21 = Rm[7] * s2, r22 = Rm[8] * s2;

    // ---- per-ray data (broadcast load: all lanes same address) ----
    float ox = raypos[r * 3 + 0], oy = raypos[r * 3 + 1], oz = raypos[r * 3 + 2];
    float dx = raydir[r * 3 + 0], dy = raydir[r * 3 + 1], dz = raydir[r * 3 + 2];
    float tmin = tminmax[r * 2 + 0];
    float tmax = tminmax[r * 2 + 1];

    // ---- exact per-lane inside interval:  y(t) = A + t*B,  |y_a| <= 1 ----
    float qx = ox - px, qy = oy - py, qz = oz - pz;
    float A0 = fmaf(r00, qx, fmaf(r01, qy, r02 * qz));
    float A1 = fmaf(r10, qx, fmaf(r11, qy, r12 * qz));
    float A2 = fmaf(r20, qx, fmaf(r21, qy, r22 * qz));
    float B0 = fmaf(r00, dx, fmaf(r01, dy, r02 * dz));
    float B1 = fmaf(r10, dx, fmaf(r11, dy, r12 * dz));
    float B2 = fmaf(r20, dx, fmaf(r21, dy, r22 * dz));

    float lt0 = -1e30f, lt1 = 1e30f;
    {
        // axis 0
        if (fabsf(B0) > 1e-12f) {
            float u = (-1.0f - A0) / B0, v = (1.0f - A0) / B0;
            lt0 = fmaxf(lt0, fminf(u, v)); lt1 = fminf(lt1, fmaxf(u, v));
        } else if (fabsf(A0) > 1.0f) { lt0 = 1e30f; lt1 = -1e30f; }
        // axis 1
        if (fabsf(B1) > 1e-12f) {
            float u = (-1.0f - A1) / B1, v = (1.0f - A1) / B1;
            lt0 = fmaxf(lt0, fminf(u, v)); lt1 = fminf(lt1, fmaxf(u, v));
        } else if (fabsf(A1) > 1.0f) { lt0 = 1e30f; lt1 = -1e30f; }
        // axis 2
        if (fabsf(B2) > 1e-12f) {
            float u = (-1.0f - A2) / B2, v = (1.0f - A2) / B2;
            lt0 = fmaxf(lt0, fminf(u, v)); lt1 = fminf(lt1, fmaxf(u, v));
        } else if (fabsf(A2) > 1.0f) { lt0 = 1e30f; lt1 = -1e30f; }
    }

    // ---- warp-level loop bounds: union of lane intervals (conservative) ----
    float tEnter = (lt0 <= lt1) ? lt0 : 1e30f;
    float tExit  = (lt0 <= lt1) ? lt1 : -1e30f;
    #pragma unroll
    for (int off = 16; off; off >>= 1) {
        tEnter = fminf(tEnter, __shfl_xor_sync(FULL, tEnter, off));
        tExit  = fmaxf(tExit,  __shfl_xor_sync(FULL, tExit,  off));
    }
    float i0f = fminf(fmaxf((tEnter - tmin) * 64.0f - 0.01f, 0.0f), 65.0f);
    float i1f = fminf(fmaxf((tExit  - tmin) * 64.0f + 0.01f, -1.0f), 63.0f);
    int iStart = (int)floorf(i0f);
    int iEnd   = (int)ceilf(i1f);           // loop i in [iStart, iEnd]

    const float4* tp4 = reinterpret_cast<const float4*>(g_tpl) + lane * (MM * MM * MM);

    const bool hi16 = (lane & 16) != 0;
    const bool hi8  = (lane & 8)  != 0;

    float chacc = 0.f;   // this lane's channel accumulator (x:0-7 y:8-15 z:16-23)
    float alpha = 0.f;   // replicated on all lanes
    float4 sp = make_float4(0.f, 0.f, 0.f, 0.f);  // pending per-lane sample
    bool  havePrev = false;
    bool  saturated = false;

    #pragma unroll 1
    for (int i = iStart; i <= iEnd; i++) {
        float t = fmaf((float)i, DTSTEP, tmin);
        if (t >= tmax) break;  // exact: valid=0 forever after; flush below

        // exact inside test via interval (box is convex along the line)
        bool inside = (t >= lt0) & (t <= lt1);
        unsigned act = __ballot_sync(FULL, inside);
        if (act == 0u) continue;  // contrib exactly 0 this step

        // ---- issue this step's gather (loads fly while we reduce prev) ----
        float4 c000, c001, c010, c011, c100, c101, c110, c111;
        float  fz = 0.f, fy = 0.f, fx = 0.f;
        if (inside) {
            float y0 = fmaf(t, B0, A0);
            float y1 = fmaf(t, B1, A1);
            float y2 = fmaf(t, B2, A2);
            float gz = fmaf(y0, 7.5f, 7.5f);
            float gy = fmaf(y1, 7.5f, 7.5f);
            float gx = fmaf(y2, 7.5f, 7.5f);
            int iz = min(max((int)floorf(gz), 0), 14);
            int iy = min(max((int)floorf(gy), 0), 14);
            int ix = min(max((int)floorf(gx), 0), 14);
            fz = fminf(fmaxf(gz - (float)iz, 0.f), 1.f);
            fy = fminf(fmaxf(gy - (float)iy, 0.f), 1.f);
            fx = fminf(fmaxf(gx - (float)ix, 0.f), 1.f);
            const float4* base = tp4 + ((iz * 16 + iy) * 16 + ix);
            c000 = base[0];    c001 = base[1];
            c010 = base[16];   c011 = base[17];
            c100 = base[256];  c101 = base[257];
            c110 = base[272];  c111 = base[273];
        }

        // ---- reduce + composite previous productive step (hidden under loads)
        if (havePrev) {
            REDUCE_COMPOSITE();
            havePrev = false;
            if (alpha >= 1.0f) saturated = true;  // future contribs exactly 0
        }
        if (saturated) break;

        // ---- fold this step's trilinear tree into sp (pending) ----
        if (inside) {
            float ez = 1.f - fz, ey = 1.f - fy, ex = 1.f - fx;
            float a00 = ez * ey, a01 = ez * fy, a10 = fz * ey, a11 = fz * fy;
            float w000 = a00 * ex, w001 = a00 * fx;
            float w010 = a01 * ex, w011 = a01 * fx;
            float w100 = a10 * ex, w101 = a10 * fx;
            float w110 = a11 * ex, w111 = a11 * fx;
            sp.x = fmaf(w000, c000.x, fmaf(w001, c001.x, fmaf(w010, c010.x,
                   fmaf(w011, c011.x, fmaf(w100, c100.x, fmaf(w101, c101.x,
                   fmaf(w110, c110.x, w111 * c111.x)))))));
            sp.y = fmaf(w000, c000.y, fmaf(w001, c001.y, fmaf(w010, c010.y,
                   fmaf(w011, c011.y, fmaf(w100, c100.y, fmaf(w101, c101.y,
                   fmaf(w110, c110.y, w111 * c111.y)))))));
            sp.z = fmaf(w000, c000.z, fmaf(w001, c001.z, fmaf(w010, c010.z,
                   fmaf(w011, c011.z, fmaf(w100, c100.z, fmaf(w101, c101.z,
                   fmaf(w110, c110.z, w111 * c111.z)))))));
            sp.w = fmaf(w000, c000.w, fmaf(w001, c001.w, fmaf(w010, c010.w,
                   fmaf(w011, c011.w, fmaf(w100, c100.w, fmaf(w101, c101.w,
                   fmaf(w110, c110.w, w111 * c111.w)))))));
        } else {
            sp = make_float4(0.f, 0.f, 0.f, 0.f);
        }
        havePrev = true;
    }

    // flush pending step (loop ended via t>=tmax, step count, or bounds)
    if (havePrev && !saturated) {
        REDUCE_COMPOSITE();
    }

    // out = concat(rayrgb[3,H,W], rayalpha[1,H,W], rayrgba[4,H,W])
    if (lane == 0)  { out[0 * HW + r] = chacc; out[4 * HW + r] = chacc; }
    if (lane == 8)  { out[1 * HW + r] = chacc; out[5 * HW + r] = chacc; }
    if (lane == 16) { out[2 * HW + r] = chacc; out[6 * HW + r] = chacc; }
    if (lane == 24) { out[3 * HW + r] = alpha; out[7 * HW + r] = alpha; }
}

// ---------------------------------------------------------------------------
extern "C" void kernel_launch(void* const* d_in, const int* in_sizes, int n_in,
                              void* d_out, int out_size) {
    const float* raypos    = (const float*)d_in[0];
    const float* raydir    = (const float*)d_in[1];
    const float* tminmax   = (const float*)d_in[2];
    const float* primpos   = (const float*)d_in[3];
    const float* primrot   = (const float*)d_in[4];
    const float* primscale = (const float*)d_in[5];
    const float* template_ = (const float*)d_in[6];
    float* out = (float*)d_out;

    const int NREPACK = KPRIM * 4 * MM * MM * MM;  // 524288
    repack_kernel<<<(NREPACK + 255) / 256, 256>>>(template_);

    const int NTHREADS = HW * 32;                  // one warp per ray
    march_kernel<<<(NTHREADS + 255) / 256, 256>>>(
        raypos, raydir, tminmax, primpos, primrot, primscale, out);
}

// round 11
// speedup vs baseline: 1.0062x; 1.0062x over previous
#include <cuda_runtime.h>

#define HW      (128 * 128)     // rays
#define KPRIM   32
#define MM      16
#define NSTEPS  64
#define DTSTEP  (1.0f / 64.0f)

// Repacked template: [k][z][y][x][c], c fastest (float4 per voxel). 2 MB.
__device__ float g_tpl[KPRIM * MM * MM * MM * 4];

// ---------------------------------------------------------------------------
// Repack kernel: template[b=0][k][c][z][y][x]  ->  g_tpl[k][z][y][x][c]
// ---------------------------------------------------------------------------
__global__ void repack_kernel(const float* __restrict__ tpl) {
    int i = blockIdx.x * blockDim.x + threadIdx.x;
    const int N = KPRIM * 4 * MM * MM * MM;  // 524288
    if (i >= N) return;
    int x = i & 15;  int t = i >> 4;
    int y = t & 15;  t >>= 4;
    int z = t & 15;  t >>= 4;
    int c = t & 3;   int k = t >> 2;
    g_tpl[((((k * 16 + z) * 16 + y) * 16 + x) << 2) + c] = tpl[i];
}

// ---------------------------------------------------------------------------
// March kernel v2: one warp per ray.
//   lane = 8*grp + s :  s = step within chunk (0..7), grp = prim group (0..3)
// 8 chunks of 8 steps cover NSTEPS=64. Per chunk the 4 groups process the
// chunk's hit-prims in parallel; sampling is independent across prims AND
// steps (huge MLP). alpha(t) = min(prefix_sum(salpha*dt), 1) since salpha>=0,
// so compositing is a 3-shfl scan per chunk instead of a per-step reduce.
// ---------------------------------------------------------------------------
__global__ void __launch_bounds__(256) march_kernel(
    const float* __restrict__ raypos,
    const float* __restrict__ raydir,
    const float* __restrict__ tminmax,
    const float* __restrict__ primpos,
    const float* __restrict__ primrot,
    const float* __restrict__ primscale,
    float* __restrict__ out)
{
    const unsigned FULL = 0xffffffffu;
    int gwarp = (blockIdx.x * blockDim.x + threadIdx.x) >> 5;
    int lane  = threadIdx.x & 31;
    if (gwarp >= HW) return;
    const int r = gwarp;           // ray index
    const int s   = lane & 7;      // step-in-chunk
    const int grp = lane >> 3;     // prim group

    // ---- per-lane primitive constants (lane == prim index for setup) ----
    float px = primpos[lane * 3 + 0];
    float py = primpos[lane * 3 + 1];
    float pz = primpos[lane * 3 + 2];
    float s0 = primscale[lane * 3 + 0];
    float s1 = primscale[lane * 3 + 1];
    float s2 = primscale[lane * 3 + 2];
    const float* Rm = primrot + lane * 9;
    float r00 = Rm[0] * s0, r01 = Rm[1] * s0, r02 = Rm[2] * s0;
    float r10 = Rm[3] * s1, r11 = Rm[4] * s1, r12 = Rm[5] * s1;
    float r20 = Rm[6] * s2, r21 = Rm[7] * s2, r22 = Rm[8] * s2;

    // ---- per-ray data (broadcast loads) ----
    float ox = raypos[r * 3 + 0], oy = raypos[r * 3 + 1], oz = raypos[r * 3 + 2];
    float dx = raydir[r * 3 + 0], dy = raydir[r * 3 + 1], dz = raydir[r * 3 + 2];
    float tmin = tminmax[r * 2 + 0];
    float tmax = tminmax[r * 2 + 1];

    // ---- per-lane prim-local ray:  y(t) = A + t*B ----
    float qx = ox - px, qy = oy - py, qz = oz - pz;
    float A0 = fmaf(r00, qx, fmaf(r01, qy, r02 * qz));
    float A1 = fmaf(r10, qx, fmaf(r11, qy, r12 * qz));
    float A2 = fmaf(r20, qx, fmaf(r21, qy, r22 * qz));
    float B0 = fmaf(r00, dx, fmaf(r01, dy, r02 * dz));
    float B1 = fmaf(r10, dx, fmaf(r11, dy, r12 * dz));
    float B2 = fmaf(r20, dx, fmaf(r21, dy, r22 * dz));

    // slab interval [lt0, lt1] for the chunk-level hit filter (conservative)
    float lt0 = -1e30f, lt1 = 1e30f;
    if (fabsf(B0) > 1e-12f) {
        float u = (-1.0f - A0) / B0, v = (1.0f - A0) / B0;
        lt0 = fmaxf(lt0, fminf(u, v)); lt1 = fminf(lt1, fmaxf(u, v));
    } else if (fabsf(A0) > 1.0f) { lt0 = 1e30f; lt1 = -1e30f; }
    if (fabsf(B1) > 1e-12f) {
        float u = (-1.0f - A1) / B1, v = (1.0f - A1) / B1;
        lt0 = fmaxf(lt0, fminf(u, v)); lt1 = fminf(lt1, fmaxf(u, v));
    } else if (fabsf(A1) > 1.0f) { lt0 = 1e30f; lt1 = -1e30f; }
    if (fabsf(B2) > 1e-12f) {
        float u = (-1.0f - A2) / B2, v = (1.0f - A2) / B2;
        lt0 = fmaxf(lt0, fminf(u, v)); lt1 = fminf(lt1, fmaxf(u, v));
    } else if (fabsf(A2) > 1.0f) { lt0 = 1e30f; lt1 = -1e30f; }

    const float4* g4 = reinterpret_cast<const float4*>(g_tpl);
    const unsigned GB = 0x11111111u << grp;   // prims k with (k & 3) == grp

    float raccx = 0.f, raccy = 0.f, raccz = 0.f;
    float base = 0.f;   // running unclipped sum of salpha*dt (uniform in warp)

    #pragma unroll 1
    for (int chunk = 0; chunk < 8; ++chunk) {
        float c_lo = fmaf((float)(chunk * 8), DTSTEP, tmin);
        if (c_lo >= tmax) break;                       // all later steps invalid
        float c_hi = fmaf((float)(chunk * 8 + 7), DTSTEP, tmin);
        const float pad = 0.25f * DTSTEP;

        bool hit = (lt0 <= lt1) && (lt1 >= c_lo - pad) && (lt0 <= c_hi + pad);
        unsigned mask = __ballot_sync(FULL, hit);
        if (mask == 0u) continue;                      // contrib exactly 0

        float t = fmaf((float)(chunk * 8 + s), DTSTEP, tmin);
        bool valid = t < tmax;

        unsigned sub = mask & GB;
        int niter = __popc(sub);
        niter = max(niter, __shfl_xor_sync(FULL, niter, 8));
        niter = max(niter, __shfl_xor_sync(FULL, niter, 16));

        float spx = 0.f, spy = 0.f, spz = 0.f, spw = 0.f;

        #pragma unroll 1
        for (int j = 0; j < niter; ++j) {
            bool active = (sub != 0u);
            int k = active ? (__ffs(sub) - 1) : 0;
            sub &= (sub - 1u);
            float a0 = __shfl_sync(FULL, A0, k);
            float a1 = __shfl_sync(FULL, A1, k);
            float a2 = __shfl_sync(FULL, A2, k);
            float b0 = __shfl_sync(FULL, B0, k);
            float b1 = __shfl_sync(FULL, B1, k);
            float b2 = __shfl_sync(FULL, B2, k);
            float y0 = fmaf(t, b0, a0);
            float y1 = fmaf(t, b1, a1);
            float y2 = fmaf(t, b2, a2);
            bool inside = active && valid &&
                          (fabsf(y0) <= 1.f) & (fabsf(y1) <= 1.f) & (fabsf(y2) <= 1.f);
            if (inside) {
                float gz = fmaf(y0, 7.5f, 7.5f);
                float gy = fmaf(y1, 7.5f, 7.5f);
                float gx = fmaf(y2, 7.5f, 7.5f);
                int iz = min(max((int)floorf(gz), 0), 14);
                int iy = min(max((int)floorf(gy), 0), 14);
                int ix = min(max((int)floorf(gx), 0), 14);
                float fz = fminf(fmaxf(gz - (float)iz, 0.f), 1.f);
                float fy = fminf(fmaxf(gy - (float)iy, 0.f), 1.f);
                float fx = fminf(fmaxf(gx - (float)ix, 0.f), 1.f);
                const float4* bp = g4 + (k << 12) + ((iz * 16 + iy) * 16 + ix);
                float4 c000 = bp[0],   c001 = bp[1];
                float4 c010 = bp[16],  c011 = bp[17];
                float4 c100 = bp[256], c101 = bp[257];
                float4 c110 = bp[272], c111 = bp[273];
                float ez = 1.f - fz, ey = 1.f - fy, ex = 1.f - fx;
                float a00 = ez * ey, a01 = ez * fy, a10 = fz * ey, a11 = fz * fy;
                float w000 = a00 * ex, w001 = a00 * fx;
                float w010 = a01 * ex, w011 = a01 * fx;
                float w100 = a10 * ex, w101 = a10 * fx;
                float w110 = a11 * ex, w111 = a11 * fx;
                spx = fmaf(w000,c000.x, fmaf(w001,c001.x, fmaf(w010,c010.x,
                      fmaf(w011,c011.x, fmaf(w100,c100.x, fmaf(w101,c101.x,
                      fmaf(w110,c110.x, fmaf(w111,c111.x, spx))))))));
                spy = fmaf(w000,c000.y, fmaf(w001,c001.y, fmaf(w010,c010.y,
                      fmaf(w011,c011.y, fmaf(w100,c100.y, fmaf(w101,c101.y,
                      fmaf(w110,c110.y, fmaf(w111,c111.y, spy))))))));
                spz = fmaf(w000,c000.z, fmaf(w001,c001.z, fmaf(w010,c010.z,
                      fmaf(w011,c011.z, fmaf(w100,c100.z, fmaf(w101,c101.z,
                      fmaf(w110,c110.z, fmaf(w111,c111.z, spz))))))));
                spw = fmaf(w000,c000.w, fmaf(w001,c001.w, fmaf(w010,c010.w,
                      fmaf(w011,c011.w, fmaf(w100,c100.w, fmaf(w101,c101.w,
                      fmaf(w110,c110.w, fmaf(w111,c111.w, spw))))))));
            }
        }

        // sum the 4 prim-groups: lanes {s, s+8, s+16, s+24} -> full per-step sample
        spx += __shfl_xor_sync(FULL, spx, 8);
        spy += __shfl_xor_sync(FULL, spy, 8);
        spz += __shfl_xor_sync(FULL, spz, 8);
        spw += __shfl_xor_sync(FULL, spw, 8);
        spx += __shfl_xor_sync(FULL, spx, 16);
        spy += __shfl_xor_sync(FULL, spy, 16);
        spz += __shfl_xor_sync(FULL, spz, 16);
        spw += __shfl_xor_sync(FULL, spw, 16);

        // inclusive prefix of salpha*dt over s (identical in all 4 subgroups)
        float sv = spw * DTSTEP;
        float incl = sv, v;
        v = __shfl_up_sync(FULL, incl, 1); if (s >= 1) incl += v;
        v = __shfl_up_sync(FULL, incl, 2); if (s >= 2) incl += v;
        v = __shfl_up_sync(FULL, incl, 4); if (s >= 4) incl += v;
        float excl = __shfl_up_sync(FULL, incl, 1); if (s == 0) excl = 0.f;

        float ai = fminf(base + incl, 1.f);
        float ap = fminf(base + excl, 1.f);
        float contrib = ai - ap;
        if (grp == 0) {   // only one subgroup accumulates rgb (avoid 4x count)
            raccx = fmaf(spx, contrib, raccx);
            raccy = fmaf(spy, contrib, raccy);
            raccz = fmaf(spz, contrib, raccz);
        }
        base += __shfl_sync(FULL, incl, 7);
        if (base >= 1.0f) break;   // saturated: all later contribs exactly 0
    }

    // reduce rgb over lanes (only grp==0 lanes are nonzero)
    #pragma unroll
    for (int off = 16; off; off >>= 1) {
        raccx += __shfl_xor_sync(FULL, raccx, off);
        raccy += __shfl_xor_sync(FULL, raccy, off);
        raccz += __shfl_xor_sync(FULL, raccz, off);
    }
    float alpha = fminf(base, 1.0f);

    if (lane == 0) {
        // out = concat(rayrgb[3,H,W], rayalpha[1,H,W], rayrgba[4,H,W])
        out[0 * HW + r] = raccx;
        out[1 * HW + r] = raccy;
        out[2 * HW + r] = raccz;
        out[3 * HW + r] = alpha;
        out[4 * HW + r] = raccx;
        out[5 * HW + r] = raccy;
        out[6 * HW + r] = raccz;
        out[7 * HW + r] = alpha;
    }
}

// ---------------------------------------------------------------------------
extern "C" void kernel_launch(void* const* d_in, const int* in_sizes, int n_in,
                              void* d_out, int out_size) {
    const float* raypos    = (const float*)d_in[0];
    const float* raydir    = (const float*)d_in[1];
    const float* tminmax   = (const float*)d_in[2];
    const float* primpos   = (const float*)d_in[3];
    const float* primrot   = (const float*)d_in[4];
    const float* primscale = (const float*)d_in[5];
    const float* template_ = (const float*)d_in[6];
    float* out = (float*)d_out;

    const int NREPACK = KPRIM * 4 * MM * MM * MM;  // 524288
    repack_kernel<<<(NREPACK + 255) / 256, 256>>>(template_);

    const int NTHREADS = HW * 32;                  // one warp per ray
    march_kernel<<<(NTHREADS + 255) / 256, 256>>>(
        raypos, raydir, tminmax, primpos, primrot, primscale, out);
}

// round 12
// speedup vs baseline: 1.4178x; 1.4091x over previous
#include <cuda_runtime.h>
#include <cuda_fp16.h>

#define HW      (128 * 128)     // rays
#define KPRIM   32
#define MM      16
#define NSTEPS  64
#define DTSTEP  (1.0f / 64.0f)

// fp16 template, x-pair packed: entry (k,z,y,x) = 16B holding
// {v[x].c0..c3, v[x+1].c0..c3} as 8 halves. 32*4096*16B = 2 MB.
__device__ __half g_tplh[KPRIM * MM * MM * MM * 8];

// ---------------------------------------------------------------------------
// Repack: template[b=0][k][c][z][y][x] (f32) -> g_tplh[k][z][y][x][pair]
// ---------------------------------------------------------------------------
__global__ void repack_kernel(const float* __restrict__ tpl) {
    int i = blockIdx.x * blockDim.x + threadIdx.x;   // entry index
    const int N = KPRIM * MM * MM * MM;              // 131072
    if (i >= N) return;
    int k = i >> 12, rem = i & 4095;
    int z = rem >> 8, y = (rem >> 4) & 15, x = rem & 15;
    int x1 = min(x + 1, 15);
    const float* base = tpl + (size_t)k * 4 * 4096 + z * 256 + y * 16;
    __half2* o = reinterpret_cast<__half2*>(g_tplh) + i * 4;
    o[0] = __floats2half2_rn(base[0 * 4096 + x],  base[1 * 4096 + x]);
    o[1] = __floats2half2_rn(base[2 * 4096 + x],  base[3 * 4096 + x]);
    o[2] = __floats2half2_rn(base[0 * 4096 + x1], base[1 * 4096 + x1]);
    o[3] = __floats2half2_rn(base[2 * 4096 + x1], base[3 * 4096 + x1]);
}

// unpack one 16B entry -> two float4 corners (voxel x, voxel x+1)
__device__ __forceinline__ void cvt8(uint4 L, float4& a, float4& b) {
    float2 t0 = __half22float2(*reinterpret_cast<__half2*>(&L.x));
    float2 t1 = __half22float2(*reinterpret_cast<__half2*>(&L.y));
    float2 t2 = __half22float2(*reinterpret_cast<__half2*>(&L.z));
    float2 t3 = __half22float2(*reinterpret_cast<__half2*>(&L.w));
    a = make_float4(t0.x, t0.y, t1.x, t1.y);
    b = make_float4(t2.x, t2.y, t3.x, t3.y);
}

// ---------------------------------------------------------------------------
// March kernel: one warp per ray. lane = 8*grp + s.
// Per chunk of 8 steps: groups process hit-prims in parallel; sampling is
// independent across prims and steps; alpha via clipped prefix sum.
// ---------------------------------------------------------------------------
__global__ void __launch_bounds__(256) march_kernel(
    const float* __restrict__ raypos,
    const float* __restrict__ raydir,
    const float* __restrict__ tminmax,
    const float* __restrict__ primpos,
    const float* __restrict__ primrot,
    const float* __restrict__ primscale,
    float* __restrict__ out)
{
    const unsigned FULL = 0xffffffffu;
    int gwarp = (blockIdx.x * blockDim.x + threadIdx.x) >> 5;
    int lane  = threadIdx.x & 31;
    if (gwarp >= HW) return;
    const int r = gwarp;
    const int s   = lane & 7;
    const int grp = lane >> 3;

    // ---- per-lane primitive constants (lane == prim index for setup) ----
    float px = primpos[lane * 3 + 0];
    float py = primpos[lane * 3 + 1];
    float pz = primpos[lane * 3 + 2];
    float s0 = primscale[lane * 3 + 0];
    float s1 = primscale[lane * 3 + 1];
    float s2 = primscale[lane * 3 + 2];
    const float* Rm = primrot + lane * 9;
    float r00 = Rm[0] * s0, r01 = Rm[1] * s0, r02 = Rm[2] * s0;
    float r10 = Rm[3] * s1, r11 = Rm[4] * s1, r12 = Rm[5] * s1;
    float r20 = Rm[6] * s2, r21 = Rm[7] * s2, r22 = Rm[8] * s2;

    // ---- per-ray data ----
    float ox = raypos[r * 3 + 0], oy = raypos[r * 3 + 1], oz = raypos[r * 3 + 2];
    float dx = raydir[r * 3 + 0], dy = raydir[r * 3 + 1], dz = raydir[r * 3 + 2];
    float tmin = tminmax[r * 2 + 0];
    float tmax = tminmax[r * 2 + 1];

    // ---- per-lane prim-local ray:  y(t) = A + t*B ----
    float qx = ox - px, qy = oy - py, qz = oz - pz;
    float A0 = fmaf(r00, qx, fmaf(r01, qy, r02 * qz));
    float A1 = fmaf(r10, qx, fmaf(r11, qy, r12 * qz));
    float A2 = fmaf(r20, qx, fmaf(r21, qy, r22 * qz));
    float B0 = fmaf(r00, dx, fmaf(r01, dy, r02 * dz));
    float B1 = fmaf(r10, dx, fmaf(r11, dy, r12 * dz));
    float B2 = fmaf(r20, dx, fmaf(r21, dy, r22 * dz));

    // slab interval for the chunk-level hit filter (conservative)
    float lt0 = -1e30f, lt1 = 1e30f;
    if (fabsf(B0) > 1e-12f) {
        float u = (-1.0f - A0) / B0, v = (1.0f - A0) / B0;
        lt0 = fmaxf(lt0, fminf(u, v)); lt1 = fminf(lt1, fmaxf(u, v));
    } else if (fabsf(A0) > 1.0f) { lt0 = 1e30f; lt1 = -1e30f; }
    if (fabsf(B1) > 1e-12f) {
        float u = (-1.0f - A1) / B1, v = (1.0f - A1) / B1;
        lt0 = fmaxf(lt0, fminf(u, v)); lt1 = fminf(lt1, fmaxf(u, v));
    } else if (fabsf(A1) > 1.0f) { lt0 = 1e30f; lt1 = -1e30f; }
    if (fabsf(B2) > 1e-12f) {
        float u = (-1.0f - A2) / B2, v = (1.0f - A2) / B2;
        lt0 = fmaxf(lt0, fminf(u, v)); lt1 = fminf(lt1, fmaxf(u, v));
    } else if (fabsf(A2) > 1.0f) { lt0 = 1e30f; lt1 = -1e30f; }

    const uint4* g16 = reinterpret_cast<const uint4*>(g_tplh);
    const unsigned GB = 0x11111111u << grp;

    float raccx = 0.f, raccy = 0.f, raccz = 0.f;
    float base = 0.f;

    #pragma unroll 1
    for (int chunk = 0; chunk < 8; ++chunk) {
        float c_lo = fmaf((float)(chunk * 8), DTSTEP, tmin);
        if (c_lo >= tmax) break;
        float c_hi = fmaf((float)(chunk * 8 + 7), DTSTEP, tmin);
        const float pad = 0.25f * DTSTEP;

        bool hit = (lt0 <= lt1) && (lt1 >= c_lo - pad) && (lt0 <= c_hi + pad);
        unsigned mask = __ballot_sync(FULL, hit);
        if (mask == 0u) continue;

        float t = fmaf((float)(chunk * 8 + s), DTSTEP, tmin);
        bool valid = t < tmax;

        unsigned sub = mask & GB;
        int niter = __popc(sub);
        niter = max(niter, __shfl_xor_sync(FULL, niter, 8));
        niter = max(niter, __shfl_xor_sync(FULL, niter, 16));

        float spx = 0.f, spy = 0.f, spz = 0.f, spw = 0.f;

        #pragma unroll 1
        for (int j = 0; j < niter; ++j) {
            bool active = (sub != 0u);
            int k = active ? (__ffs(sub) - 1) : 0;
            sub &= (sub - 1u);
            float a0 = __shfl_sync(FULL, A0, k);
            float a1 = __shfl_sync(FULL, A1, k);
            float a2 = __shfl_sync(FULL, A2, k);
            float b0 = __shfl_sync(FULL, B0, k);
            float b1 = __shfl_sync(FULL, B1, k);
            float b2 = __shfl_sync(FULL, B2, k);
            float y0 = fmaf(t, b0, a0);
            float y1 = fmaf(t, b1, a1);
            float y2 = fmaf(t, b2, a2);
            bool inside = active && valid &&
                          (fabsf(y0) <= 1.f) & (fabsf(y1) <= 1.f) & (fabsf(y2) <= 1.f);
            if (inside) {
                float gz = fmaf(y0, 7.5f, 7.5f);
                float gy = fmaf(y1, 7.5f, 7.5f);
                float gx = fmaf(y2, 7.5f, 7.5f);
                int iz = min(max((int)floorf(gz), 0), 14);
                int iy = min(max((int)floorf(gy), 0), 14);
                int ix = min(max((int)floorf(gx), 0), 14);
                float fz = fminf(fmaxf(gz - (float)iz, 0.f), 1.f);
                float fy = fminf(fmaxf(gy - (float)iy, 0.f), 1.f);
                float fx = fminf(fmaxf(gx - (float)ix, 0.f), 1.f);
                const uint4* bp = g16 + (k << 12) + ((iz * 16 + iy) * 16 + ix);
                uint4 L00 = bp[0];      // (iz  ,iy  ,ix) + x-pair
                uint4 L01 = bp[16];     // (iz  ,iy+1,ix)
                uint4 L10 = bp[256];    // (iz+1,iy  ,ix)
                uint4 L11 = bp[272];    // (iz+1,iy+1,ix)
                float4 c000, c001, c010, c011, c100, c101, c110, c111;
                cvt8(L00, c000, c001);
                cvt8(L01, c010, c011);
                cvt8(L10, c100, c101);
                cvt8(L11, c110, c111);
                float ez = 1.f - fz, ey = 1.f - fy, ex = 1.f - fx;
                float a00 = ez * ey, a01 = ez * fy, a10 = fz * ey, a11 = fz * fy;
                float w000 = a00 * ex, w001 = a00 * fx;
                float w010 = a01 * ex, w011 = a01 * fx;
                float w100 = a10 * ex, w101 = a10 * fx;
                float w110 = a11 * ex, w111 = a11 * fx;
                spx = fmaf(w000,c000.x, fmaf(w001,c001.x, fmaf(w010,c010.x,
                      fmaf(w011,c011.x, fmaf(w100,c100.x, fmaf(w101,c101.x,
                      fmaf(w110,c110.x, fmaf(w111,c111.x, spx))))))));
                spy = fmaf(w000,c000.y, fmaf(w001,c001.y, fmaf(w010,c010.y,
                      fmaf(w011,c011.y, fmaf(w100,c100.y, fmaf(w101,c101.y,
                      fmaf(w110,c110.y, fmaf(w111,c111.y, spy))))))));
                spz = fmaf(w000,c000.z, fmaf(w001,c001.z, fmaf(w010,c010.z,
                      fmaf(w011,c011.z, fmaf(w100,c100.z, fmaf(w101,c101.z,
                      fmaf(w110,c110.z, fmaf(w111,c111.z, spz))))))));
                spw = fmaf(w000,c000.w, fmaf(w001,c001.w, fmaf(w010,c010.w,
                      fmaf(w011,c011.w, fmaf(w100,c100.w, fmaf(w101,c101.w,
                      fmaf(w110,c110.w, fmaf(w111,c111.w, spw))))))));
            }
        }

        // sum the 4 prim-groups
        spx += __shfl_xor_sync(FULL, spx, 8);
        spy += __shfl_xor_sync(FULL, spy, 8);
        spz += __shfl_xor_sync(FULL, spz, 8);
        spw += __shfl_xor_sync(FULL, spw, 8);
        spx += __shfl_xor_sync(FULL, spx, 16);
        spy += __shfl_xor_sync(FULL, spy, 16);
        spz += __shfl_xor_sync(FULL, spz, 16);
        spw += __shfl_xor_sync(FULL, spw, 16);

        // inclusive prefix of salpha*dt over s
        float sv = spw * DTSTEP;
        float incl = sv, v;
        v = __shfl_up_sync(FULL, incl, 1); if (s >= 1) incl += v;
        v = __shfl_up_sync(FULL, incl, 2); if (s >= 2) incl += v;
        v = __shfl_up_sync(FULL, incl, 4); if (s >= 4) incl += v;
        float excl = __shfl_up_sync(FULL, incl, 1); if (s == 0) excl = 0.f;

        float ai = fminf(base + incl, 1.f);
        float ap = fminf(base + excl, 1.f);
        float contrib = ai - ap;
        if (grp == 0) {
            raccx = fmaf(spx, contrib, raccx);
            raccy = fmaf(spy, contrib, raccy);
            raccz = fmaf(spz, contrib, raccz);
        }
        base += __shfl_sync(FULL, incl, 7);
        if (base >= 1.0f) break;
    }

    #pragma unroll
    for (int off = 16; off; off >>= 1) {
        raccx += __shfl_xor_sync(FULL, raccx, off);
        raccy += __shfl_xor_sync(FULL, raccy, off);
        raccz += __shfl_xor_sync(FULL, raccz, off);
    }
    float alpha = fminf(base, 1.0f);

    if (lane == 0) {
        out[0 * HW + r] = raccx;
        out[1 * HW + r] = raccy;
        out[2 * HW + r] = raccz;
        out[3 * HW + r] = alpha;
        out[4 * HW + r] = raccx;
        out[5 * HW + r] = raccy;
        out[6 * HW + r] = raccz;
        out[7 * HW + r] = alpha;
    }
}

// ---------------------------------------------------------------------------
extern "C" void kernel_launch(void* const* d_in, const int* in_sizes, int n_in,
                              void* d_out, int out_size) {
    const float* raypos    = (const float*)d_in[0];
    const float* raydir    = (const float*)d_in[1];
    const float* tminmax   = (const float*)d_in[2];
    const float* primpos   = (const float*)d_in[3];
    const float* primrot   = (const float*)d_in[4];
    const float* primscale = (const float*)d_in[5];
    const float* template_ = (const float*)d_in[6];
    float* out = (float*)d_out;

    const int NREPACK = KPRIM * MM * MM * MM;      // 131072 entries
    repack_kernel<<<(NREPACK + 255) / 256, 256>>>(template_);

    const int NTHREADS = HW * 32;                  // one warp per ray
    march_kernel<<<(NTHREADS + 255) / 256, 256>>>(
        raypos, raydir, tminmax, primpos, primrot, primscale, out);
}

// round 13
// speedup vs baseline: 1.4303x; 1.0088x over previous
#include <cuda_runtime.h>
#include <cuda_fp16.h>

#define HW      (128 * 128)     // rays
#define KPRIM   32
#define MM      16
#define NSTEPS  64
#define DTSTEP  (1.0f / 64.0f)

// fp16 template, x-pair packed: entry (k,z,y,x) = 16B holding
// {v[x].c0..c3, v[x+1].c0..c3} as 8 halves. 32*4096*16B = 2 MB.
__device__ __half g_tplh[KPRIM * MM * MM * MM * 8];

// ---------------------------------------------------------------------------
// Repack: template[b=0][k][c][z][y][x] (f32) -> g_tplh[k][z][y][x][pair]
// ---------------------------------------------------------------------------
__global__ void repack_kernel(const float* __restrict__ tpl) {
    int i = blockIdx.x * blockDim.x + threadIdx.x;   // entry index
    const int N = KPRIM * MM * MM * MM;              // 131072
    if (i >= N) return;
    int k = i >> 12, rem = i & 4095;
    int z = rem >> 8, y = (rem >> 4) & 15, x = rem & 15;
    int x1 = min(x + 1, 15);
    const float* base = tpl + (size_t)k * 4 * 4096 + z * 256 + y * 16;
    __half2* o = reinterpret_cast<__half2*>(g_tplh) + i * 4;
    o[0] = __floats2half2_rn(base[0 * 4096 + x],  base[1 * 4096 + x]);
    o[1] = __floats2half2_rn(base[2 * 4096 + x],  base[3 * 4096 + x]);
    o[2] = __floats2half2_rn(base[0 * 4096 + x1], base[1 * 4096 + x1]);
    o[3] = __floats2half2_rn(base[2 * 4096 + x1], base[3 * 4096 + x1]);
}

// unpack one 16B entry -> two float4 corners (voxel x, voxel x+1)
__device__ __forceinline__ void cvt8(uint4 L, float4& a, float4& b) {
    float2 t0 = __half22float2(*reinterpret_cast<__half2*>(&L.x));
    float2 t1 = __half22float2(*reinterpret_cast<__half2*>(&L.y));
    float2 t2 = __half22float2(*reinterpret_cast<__half2*>(&L.z));
    float2 t3 = __half22float2(*reinterpret_cast<__half2*>(&L.w));
    a = make_float4(t0.x, t0.y, t1.x, t1.y);
    b = make_float4(t2.x, t2.y, t3.x, t3.y);
}

// ---------------------------------------------------------------------------
// March kernel: one warp per ray. lane = 8*grp + s.
// Per chunk of 8 steps: the 4 groups consume the compacted hit list
// round-robin (group g takes hits g, g+4, g+8 ... via __fns) -> perfectly
// balanced, niter = ceil(nhits/4) warp-uniform. alpha via clipped prefix sum.
// ---------------------------------------------------------------------------
__global__ void __launch_bounds__(256) march_kernel(
    const float* __restrict__ raypos,
    const float* __restrict__ raydir,
    const float* __restrict__ tminmax,
    const float* __restrict__ primpos,
    const float* __restrict__ primrot,
    const float* __restrict__ primscale,
    float* __restrict__ out)
{
    const unsigned FULL = 0xffffffffu;
    int gwarp = (blockIdx.x * blockDim.x + threadIdx.x) >> 5;
    int lane  = threadIdx.x & 31;
    if (gwarp >= HW) return;
    const int r = gwarp;
    const int s   = lane & 7;
    const int grp = lane >> 3;

    // ---- per-lane primitive constants (lane == prim index for setup) ----
    float px = primpos[lane * 3 + 0];
    float py = primpos[lane * 3 + 1];
    float pz = primpos[lane * 3 + 2];
    float s0 = primscale[lane * 3 + 0];
    float s1 = primscale[lane * 3 + 1];
    float s2 = primscale[lane * 3 + 2];
    const float* Rm = primrot + lane * 9;
    float r00 = Rm[0] * s0, r01 = Rm[1] * s0, r02 = Rm[2] * s0;
    float r10 = Rm[3] * s1, r11 = Rm[4] * s1, r12 = Rm[5] * s1;
    float r20 = Rm[6] * s2, r21 = Rm[7] * s2, r22 = Rm[8] * s2;

    // ---- per-ray data ----
    float ox = raypos[r * 3 + 0], oy = raypos[r * 3 + 1], oz = raypos[r * 3 + 2];
    float dx = raydir[r * 3 + 0], dy = raydir[r * 3 + 1], dz = raydir[r * 3 + 2];
    float tmin = tminmax[r * 2 + 0];
    float tmax = tminmax[r * 2 + 1];

    // ---- per-lane prim-local ray:  y(t) = A + t*B ----
    float qx = ox - px, qy = oy - py, qz = oz - pz;
    float A0 = fmaf(r00, qx, fmaf(r01, qy, r02 * qz));
    float A1 = fmaf(r10, qx, fmaf(r11, qy, r12 * qz));
    float A2 = fmaf(r20, qx, fmaf(r21, qy, r22 * qz));
    float B0 = fmaf(r00, dx, fmaf(r01, dy, r02 * dz));
    float B1 = fmaf(r10, dx, fmaf(r11, dy, r12 * dz));
    float B2 = fmaf(r20, dx, fmaf(r21, dy, r22 * dz));

    // slab interval for the chunk-level hit filter (conservative)
    float lt0 = -1e30f, lt1 = 1e30f;
    if (fabsf(B0) > 1e-12f) {
        float u = (-1.0f - A0) / B0, v = (1.0f - A0) / B0;
        lt0 = fmaxf(lt0, fminf(u, v)); lt1 = fminf(lt1, fmaxf(u, v));
    } else if (fabsf(A0) > 1.0f) { lt0 = 1e30f; lt1 = -1e30f; }
    if (fabsf(B1) > 1e-12f) {
        float u = (-1.0f - A1) / B1, v = (1.0f - A1) / B1;
        lt0 = fmaxf(lt0, fminf(u, v)); lt1 = fminf(lt1, fmaxf(u, v));
    } else if (fabsf(A1) > 1.0f) { lt0 = 1e30f; lt1 = -1e30f; }
    if (fabsf(B2) > 1e-12f) {
        float u = (-1.0f - A2) / B2, v = (1.0f - A2) / B2;
        lt0 = fmaxf(lt0, fminf(u, v)); lt1 = fminf(lt1, fmaxf(u, v));
    } else if (fabsf(A2) > 1.0f) { lt0 = 1e30f; lt1 = -1e30f; }

    const uint4* g16 = reinterpret_cast<const uint4*>(g_tplh);

    float raccx = 0.f, raccy = 0.f, raccz = 0.f;
    float base = 0.f;

    #pragma unroll 1
    for (int chunk = 0; chunk < 8; ++chunk) {
        float c_lo = fmaf((float)(chunk * 8), DTSTEP, tmin);
        if (c_lo >= tmax) break;
        float c_hi = fmaf((float)(chunk * 8 + 7), DTSTEP, tmin);
        const float pad = 0.25f * DTSTEP;

        bool hit = (lt0 <= lt1) && (lt1 >= c_lo - pad) && (lt0 <= c_hi + pad);
        unsigned mask = __ballot_sync(FULL, hit);
        if (mask == 0u) continue;

        float t = fmaf((float)(chunk * 8 + s), DTSTEP, tmin);
        bool valid = t < tmax;

        int niter = (__popc(mask) + 3) >> 2;   // balanced, warp-uniform

        float spx = 0.f, spy = 0.f, spz = 0.f, spw = 0.f;

        #pragma unroll 1
        for (int j = 0; j < niter; ++j) {
            // group g consumes the (4j+g)-th set bit of the hit mask
            unsigned k = __fns(mask, 0, 4 * j + grp + 1);
            bool active = (k < 32u);
            int kk = active ? (int)k : 0;
            float a0 = __shfl_sync(FULL, A0, kk);
            float a1 = __shfl_sync(FULL, A1, kk);
            float a2 = __shfl_sync(FULL, A2, kk);
            float b0 = __shfl_sync(FULL, B0, kk);
            float b1 = __shfl_sync(FULL, B1, kk);
            float b2 = __shfl_sync(FULL, B2, kk);
            float y0 = fmaf(t, b0, a0);
            float y1 = fmaf(t, b1, a1);
            float y2 = fmaf(t, b2, a2);
            bool inside = active && valid &&
                          (fabsf(y0) <= 1.f) & (fabsf(y1) <= 1.f) & (fabsf(y2) <= 1.f);
            if (inside) {
                float gz = fmaf(y0, 7.5f, 7.5f);
                float gy = fmaf(y1, 7.5f, 7.5f);
                float gx = fmaf(y2, 7.5f, 7.5f);
                int iz = min(max((int)floorf(gz), 0), 14);
                int iy = min(max((int)floorf(gy), 0), 14);
                int ix = min(max((int)floorf(gx), 0), 14);
                float fz = fminf(fmaxf(gz - (float)iz, 0.f), 1.f);
                float fy = fminf(fmaxf(gy - (float)iy, 0.f), 1.f);
                float fx = fminf(fmaxf(gx - (float)ix, 0.f), 1.f);
                const uint4* bp = g16 + (kk << 12) + ((iz * 16 + iy) * 16 + ix);
                uint4 L00 = bp[0];      // (iz  ,iy  ,ix) + x-pair
                uint4 L01 = bp[16];     // (iz  ,iy+1,ix)
                uint4 L10 = bp[256];    // (iz+1,iy  ,ix)
                uint4 L11 = bp[272];    // (iz+1,iy+1,ix)
                float4 c000, c001, c010, c011, c100, c101, c110, c111;
                cvt8(L00, c000, c001);
                cvt8(L01, c010, c011);
                cvt8(L10, c100, c101);
                cvt8(L11, c110, c111);
                float ez = 1.f - fz, ey = 1.f - fy, ex = 1.f - fx;
                float a00 = ez * ey, a01 = ez * fy, a10 = fz * ey, a11 = fz * fy;
                float w000 = a00 * ex, w001 = a00 * fx;
                float w010 = a01 * ex, w011 = a01 * fx;
                float w100 = a10 * ex, w101 = a10 * fx;
                float w110 = a11 * ex, w111 = a11 * fx;
                spx = fmaf(w000,c000.x, fmaf(w001,c001.x, fmaf(w010,c010.x,
                      fmaf(w011,c011.x, fmaf(w100,c100.x, fmaf(w101,c101.x,
                      fmaf(w110,c110.x, fmaf(w111,c111.x, spx))))))));
                spy = fmaf(w000,c000.y, fmaf(w001,c001.y, fmaf(w010,c010.y,
                      fmaf(w011,c011.y, fmaf(w100,c100.y, fmaf(w101,c101.y,
                      fmaf(w110,c110.y, fmaf(w111,c111.y, spy))))))));
                spz = fmaf(w000,c000.z, fmaf(w001,c001.z, fmaf(w010,c010.z,
                      fmaf(w011,c011.z, fmaf(w100,c100.z, fmaf(w101,c101.z,
                      fmaf(w110,c110.z, fmaf(w111,c111.z, spz))))))));
                spw = fmaf(w000,c000.w, fmaf(w001,c001.w, fmaf(w010,c010.w,
                      fmaf(w011,c011.w, fmaf(w100,c100.w, fmaf(w101,c101.w,
                      fmaf(w110,c110.w, fmaf(w111,c111.w, spw))))))));
            }
        }

        // sum the 4 prim-groups
        spx += __shfl_xor_sync(FULL, spx, 8);
        spy += __shfl_xor_sync(FULL, spy, 8);
        spz += __shfl_xor_sync(FULL, spz, 8);
        spw += __shfl_xor_sync(FULL, spw, 8);
        spx += __shfl_xor_sync(FULL, spx, 16);
        spy += __shfl_xor_sync(FULL, spy, 16);
        spz += __shfl_xor_sync(FULL, spz, 16);
        spw += __shfl_xor_sync(FULL, spw, 16);

        // inclusive prefix of salpha*dt over s
        float sv = spw * DTSTEP;
        float incl = sv, v;
        v = __shfl_up_sync(FULL, incl, 1); if (s >= 1) incl += v;
        v = __shfl_up_sync(FULL, incl, 2); if (s >= 2) incl += v;
        v = __shfl_up_sync(FULL, incl, 4); if (s >= 4) incl += v;
        float excl = __shfl_up_sync(FULL, incl, 1); if (s == 0) excl = 0.f;

        float ai = fminf(base + incl, 1.f);
        float ap = fminf(base + excl, 1.f);
        float contrib = ai - ap;
        if (grp == 0) {
            raccx = fmaf(spx, contrib, raccx);
            raccy = fmaf(spy, contrib, raccy);
            raccz = fmaf(spz, contrib, raccz);
        }
        base += __shfl_sync(FULL, incl, 7);
        if (base >= 1.0f) break;
    }

    #pragma unroll
    for (int off = 16; off; off >>= 1) {
        raccx += __shfl_xor_sync(FULL, raccx, off);
        raccy += __shfl_xor_sync(FULL, raccy, off);
        raccz += __shfl_xor_sync(FULL, raccz, off);
    }
    float alpha = fminf(base, 1.0f);

    if (lane == 0) {
        out[0 * HW + r] = raccx;
        out[1 * HW + r] = raccy;
        out[2 * HW + r] = raccz;
        out[3 * HW + r] = alpha;
        out[4 * HW + r] = raccx;
        out[5 * HW + r] = raccy;
        out[6 * HW + r] = raccz;
        out[7 * HW + r] = alpha;
    }
}

// ---------------------------------------------------------------------------
extern "C" void kernel_launch(void* const* d_in, const int* in_sizes, int n_in,
                              void* d_out, int out_size) {
    const float* raypos    = (const float*)d_in[0];
    const float* raydir    = (const float*)d_in[1];
    const float* tminmax   = (const float*)d_in[2];
    const float* primpos   = (const float*)d_in[3];
    const float* primrot   = (const float*)d_in[4];
    const float* primscale = (const float*)d_in[5];
    const float* template_ = (const float*)d_in[6];
    float* out = (float*)d_out;

    const int NREPACK = KPRIM * MM * MM * MM;      // 131072 entries
    repack_kernel<<<(NREPACK + 255) / 256, 256>>>(template_);

    const int NTHREADS = HW * 32;                  // one warp per ray
    march_kernel<<<(NTHREADS + 255) / 256, 256>>>(
        raypos, raydir, tminmax, primpos, primrot, primscale, out);
}